// round 7
// baseline (speedup 1.0000x reference)
#include <cuda_runtime.h>

// Problem constants: T=1024, B=64, I=512, H=512, 3H=1536
#define NCTA 128   // persistent recurrent kernel grid (<= 148 SMs -> all co-resident)

// ---------------- device-global scratch (no allocation allowed) ----------------
__device__ float g_gx[100663296];                 // [1024*64, 1536] input gate pre-acts
__device__ __align__(16) float g_hP[2][32768];    // ping-pong h, PAIRED-K: [256 kp][64 b][2]
__device__ unsigned int g_flag[NCTA];             // per-CTA publish counters (monotonic)

// ---------------- f32x2 packed-math helpers (Blackwell, PTX-only path) ----------
__device__ __forceinline__ void ffma2(unsigned long long &acc, unsigned long long a,
                                      unsigned long long b) {
    asm("fma.rn.f32x2 %0, %1, %2, %0;" : "+l"(acc) : "l"(a), "l"(b));
}
__device__ __forceinline__ unsigned long long dup2(float a) {
    unsigned long long r; asm("mov.b64 %0, {%1, %1};" : "=l"(r) : "f"(a)); return r;
}
__device__ __forceinline__ unsigned long long pack2(float lo, float hi) {
    unsigned long long r; asm("mov.b64 %0, {%1, %2};" : "=l"(r) : "f"(lo), "f"(hi)); return r;
}
__device__ __forceinline__ float sum2(unsigned long long v) {
    float lo, hi; asm("mov.b64 {%0, %1}, %2;" : "=f"(lo), "=f"(hi) : "l"(v)); return lo + hi;
}
__device__ __forceinline__ float2 unpack2(unsigned long long v) {
    float2 f; asm("mov.b64 {%0, %1}, %2;" : "=f"(f.x), "=f"(f.y) : "l"(v)); return f;
}

// ---------------- flag primitives (gpu scope, L2-coherent) -----------------------
__device__ __forceinline__ unsigned int ld_acq(const unsigned int* p) {
    unsigned int v;
    asm volatile("ld.acquire.gpu.global.u32 %0, [%1];" : "=r"(v) : "l"(p) : "memory");
    return v;
}
__device__ __forceinline__ unsigned int ld_rlx(const unsigned int* p) {
    unsigned int v;
    asm volatile("ld.relaxed.gpu.global.u32 %0, [%1];" : "=r"(v) : "l"(p) : "memory");
    return v;
}
__device__ __forceinline__ void st_rel(unsigned int* p, unsigned int v) {
    asm volatile("st.release.gpu.global.u32 [%0], %1;" :: "l"(p), "r"(v) : "memory");
}
__device__ __forceinline__ void bar_sync(int id, int cnt) {
    asm volatile("bar.sync %0, %1;" :: "r"(id), "r"(cnt) : "memory");
}

// =================================================================================
// Kernel A: gx[m][n] = sum_k X[m][k] * W[n][k] + bias[n]
//   X: [65536, 512], W: [1536, 512] -> g_gx. 128x128 tile, BK=8, 8x8 microtile.
// =================================================================================
__global__ __launch_bounds__(256) void gemm_gx(const float* __restrict__ X,
                                               const float* __restrict__ W,
                                               const float* __restrict__ bias) {
    __shared__ __align__(16) float As[8][128];
    __shared__ __align__(16) float Bs[8][128];
    const int tid = threadIdx.x;
    const int m0 = blockIdx.y * 128;
    const int n0 = blockIdx.x * 128;
    const int tx = tid & 15;
    const int ty = tid >> 4;
    const int lrow = tid >> 1;
    const int lk = (tid & 1) * 4;

    unsigned long long acc[8][4];
#pragma unroll
    for (int i = 0; i < 8; i++)
#pragma unroll
        for (int jp = 0; jp < 4; jp++) acc[i][jp] = 0ull;

    const float* xg = X + (size_t)(m0 + lrow) * 512 + lk;
    const float* wg = W + (size_t)(n0 + lrow) * 512 + lk;

    for (int k0 = 0; k0 < 512; k0 += 8) {
        float4 av = *(const float4*)(xg + k0);
        float4 bv = *(const float4*)(wg + k0);
        __syncthreads();
        As[lk + 0][lrow] = av.x; As[lk + 1][lrow] = av.y;
        As[lk + 2][lrow] = av.z; As[lk + 3][lrow] = av.w;
        Bs[lk + 0][lrow] = bv.x; Bs[lk + 1][lrow] = bv.y;
        Bs[lk + 2][lrow] = bv.z; Bs[lk + 3][lrow] = bv.w;
        __syncthreads();
#pragma unroll
        for (int kk = 0; kk < 8; kk++) {
            float4 a0 = *(const float4*)&As[kk][ty * 8];
            float4 a1 = *(const float4*)&As[kk][ty * 8 + 4];
            float4 b0 = *(const float4*)&Bs[kk][tx * 8];
            float4 b1 = *(const float4*)&Bs[kk][tx * 8 + 4];
            unsigned long long bp0 = pack2(b0.x, b0.y);
            unsigned long long bp1 = pack2(b0.z, b0.w);
            unsigned long long bp2 = pack2(b1.x, b1.y);
            unsigned long long bp3 = pack2(b1.z, b1.w);
            float a[8] = {a0.x, a0.y, a0.z, a0.w, a1.x, a1.y, a1.z, a1.w};
#pragma unroll
            for (int i = 0; i < 8; i++) {
                unsigned long long ad = dup2(a[i]);
                ffma2(acc[i][0], ad, bp0);
                ffma2(acc[i][1], ad, bp1);
                ffma2(acc[i][2], ad, bp2);
                ffma2(acc[i][3], ad, bp3);
            }
        }
    }

    float bs[8];
#pragma unroll
    for (int c = 0; c < 8; c++) bs[c] = bias[n0 + tx * 8 + c];
#pragma unroll
    for (int i = 0; i < 8; i++) {
        size_t base = (size_t)(m0 + ty * 8 + i) * 1536 + n0 + tx * 8;
        float2 p0 = unpack2(acc[i][0]);
        float2 p1 = unpack2(acc[i][1]);
        float2 p2 = unpack2(acc[i][2]);
        float2 p3 = unpack2(acc[i][3]);
        float4 o0 = make_float4(p0.x + bs[0], p0.y + bs[1], p1.x + bs[2], p1.y + bs[3]);
        float4 o1 = make_float4(p2.x + bs[4], p2.y + bs[5], p3.x + bs[6], p3.y + bs[7]);
        *(float4*)&g_gx[base]     = o0;
        *(float4*)&g_gx[base + 4] = o1;
    }
}

// =================================================================================
// Kernel B: persistent GRU recurrence, producer-consumer flags, bounded sync.
//   128 CTAs x 512 threads (16 warps). CTA owns 4 units (12 gate-rows).
//   Warp = (kslice of 64k) x (bhalf of 32b); lane = (b-pair, ksub of 32k).
//   h stored paired-k (float2 (k,k+1) per b): LDG.128 -> 2 ready f32x2 operands.
//   Per step: [A] all warps poll their 16 producer flags (ALWAYS, even when the
//   ragged skip drops the FFMA work -- collectively all 128 flags, which makes
//   the depth-2 h ping-pong WAR-safe), accumulate into red[t&1].
//   [B] __syncthreads. [C] warps 0-7 reduce, gate math, publish h(t+1), release
//   flag. Warps 8-15 run into step t+1 (bounded by the next flag poll).
// =================================================================================
__global__ __launch_bounds__(512) void gru_rec(const float* __restrict__ whh,
                                               const float* __restrict__ bhh,
                                               const int* __restrict__ lens,
                                               float* __restrict__ out) {
    __shared__ __align__(16) float w_s[12][16][36];   // [row][k-chunk 32][32+4 pad]
    __shared__ __align__(16) float red[2][8][12][72]; // [par][kslice][row][64 b + 8 pad]
    __shared__ int lens_s[64];

    const int tid  = threadIdx.x;
    const int cta  = blockIdx.x;
    const int wrp  = tid >> 5;
    const int lane = tid & 31;
    const int kslice = wrp >> 1;            // 0..7 (64 k each)
    const int bhalf  = wrp & 1;             // 0..1 (32 b each)
    const int p      = lane & 15;           // b-pair within half
    const int ksub   = lane >> 4;           // 0..1 (32 k each)
    const int b0     = bhalf * 32 + 2 * p;
    const int kp0    = kslice * 32 + ksub * 16;   // first k-pair (16 pairs per lane)
    const int chunk  = kslice * 2 + ksub;

    // gate-phase mapping (tid < 256): gu fast -> h-pair publish via shfl partner
    const int gu = tid & 3;
    const int gb = (tid >> 2) & 63;
    const int j  = cta * 4 + gu;

    // Preload W_hh slice into chunked/padded SMEM (persistent across steps)
    for (int idx = tid; idx < 12 * 512; idx += 512) {
        int row = idx >> 9;
        int k   = idx & 511;
        int g   = row >> 2;
        int u   = row & 3;
        w_s[row][k >> 5][k & 31] = whh[(size_t)(g * 512 + cta * 4 + u) * 512 + k];
    }
    if (tid < 64) lens_s[tid] = lens[tid];

    // Monotonic flag base: each launch adds exactly 1025 to every flag uniformly,
    // so at launch start all 128 flags are equal. Zero-init covers launch #1.
    const unsigned int F = ld_rlx(&g_flag[cta]);

    float bh_r = 0.f, bh_z = 0.f, bh_n = 0.f;
    if (tid < 256) {
        bh_r = bhh[j];
        bh_z = bhh[512 + j];
        bh_n = bhh[1024 + j];
    }
    // h(0) = 0 into buf0 (this CTA's 2 k-pairs across all b)
    if (tid < 128) {
        int jp  = tid >> 6;
        int gb2 = tid & 63;
        float2 z = make_float2(0.f, 0.f);
        __stcg((float2*)&g_hP[0][((size_t)(cta * 2 + jp) * 64 + gb2) * 2], z);
    }
    __syncthreads();
    if (tid == 0) st_rel(&g_flag[cta], F + 1);   // h(0) published

    const int maxlen_half = lens_s[bhalf * 32];  // lengths descending-sorted
    const int len_b = lens_s[gb];
    float hreg = 0.f;

    const unsigned int* fp = &g_flag[kslice * 16 + (lane & 15)];

    for (int t = 0; t < 1024; t++) {
        // gate warps prefetch input-side gates early
        float gxr = 0.f, gxz = 0.f, gxn = 0.f;
        if (tid < 256) {
            const float* gxp = g_gx + (size_t)(t * 64 + gb) * 1536 + j;
            gxr = gxp[0];
            gxz = gxp[512];
            gxn = gxp[1024];
        }

        // [A] wait for this kslice's 16 producer CTAs to publish h(t).
        // NEVER skipped: collectively (16 warps x 16 CTAs) this CTA observes all
        // 128 flags >= F+1+t before it writes h(t+1) -> WAR-safe ping-pong, and
        // warp run-ahead is bounded to one step.
        const unsigned int tgt = F + 1 + (unsigned)t;
        while (!__all_sync(0xffffffffu, ld_acq(fp) >= tgt)) {}

        if (t < maxlen_half) {                   // warp-level ragged FFMA skip
            const float* hb = &g_hP[t & 1][((size_t)kp0 * 64 + b0) * 2];
            unsigned long long accA[12], accB[12];
#pragma unroll
            for (int r = 0; r < 12; r++) { accA[r] = 0ull; accB[r] = 0ull; }

#pragma unroll
            for (int i = 0; i < 8; i++) {        // 2 k-pairs (4 k) per iteration
                // LDG.128: {(k,k+1) b0, (k,k+1) b0+1} directly as 2x u64 operands
                ulonglong2 hA = __ldcg((const ulonglong2*)(hb + (size_t)(2 * i) * 128));
                ulonglong2 hB = __ldcg((const ulonglong2*)(hb + (size_t)(2 * i + 1) * 128));
#pragma unroll
                for (int r = 0; r < 12; r++) {
                    ulonglong2 wv = *(const ulonglong2*)&w_s[r][chunk][i * 4];
                    ffma2(accA[r], hA.x, wv.x);
                    ffma2(accB[r], hA.y, wv.x);
                    ffma2(accA[r], hB.x, wv.y);
                    ffma2(accB[r], hB.y, wv.y);
                }
            }

            // fold k-parity + ksub (shfl xor 16), store per-kslice partials (STS.64)
#pragma unroll
            for (int r = 0; r < 12; r++) {
                float sA = sum2(accA[r]);
                float sB = sum2(accB[r]);
                sA += __shfl_xor_sync(0xffffffffu, sA, 16);
                sB += __shfl_xor_sync(0xffffffffu, sB, 16);
                if (ksub == 0)
                    *(float2*)&red[t & 1][kslice][r][b0] = make_float2(sA, sB);
            }
        }

        __syncthreads();                         // [B] red[t&1] complete

        // [C] gate phase; warps 8-15 fall through into step t+1's poll
        if (tid < 256) {
            float outv = 0.f;
            if (t < len_b) {
                float ghr = bh_r, ghz = bh_z, ghn = bh_n;
#pragma unroll
                for (int ks = 0; ks < 8; ks++) {
                    ghr += red[t & 1][ks][gu][gb];
                    ghz += red[t & 1][ks][4 + gu][gb];
                    ghn += red[t & 1][ks][8 + gu][gb];
                }
                float r = 1.f / (1.f + __expf(-(gxr + ghr)));
                float z = 1.f / (1.f + __expf(-(gxz + ghz)));
                float n = tanhf(gxn + r * ghn);
                hreg = (1.f - z) * n + z * hreg;
                outv = hreg;
            }

            // publish h(t+1) pair (units j, j^1) via shfl partner
            float hpart = __shfl_xor_sync(0xffffffffu, hreg, 1);
            if ((gu & 1) == 0) {
                float2 v = make_float2(hreg, hpart);
                __stcg((float2*)&g_hP[(t + 1) & 1]
                                     [((size_t)(cta * 2 + (gu >> 1)) * 64 + gb) * 2], v);
            }
            bar_sync(1, 256);                    // gate h-stores done (cta fence)
            if (tid == 0) st_rel(&g_flag[cta], F + 2 + (unsigned)t);

            out[(size_t)t * 32768 + gb * 512 + j] = outv;  // off critical path
        }
    }

    // h_last: [1, B, H] appended after output
    if (tid < 256)
        out[(size_t)1024 * 32768 + gb * 512 + j] = hreg;
}

// =================================================================================
// Inputs (metadata order): x[T,B,I] f32, batch_lengths[B] i32, w_ih[3H,I] f32,
// w_hh[3H,H] f32, b_ih[3H] f32, b_hh[3H] f32.  Output: [T,B,H] then [1,B,H], fp32.
// =================================================================================
extern "C" void kernel_launch(void* const* d_in, const int* in_sizes, int n_in,
                              void* d_out, int out_size) {
    const float* x   = (const float*)d_in[0];
    const int*   len = (const int*)  d_in[1];
    const float* wih = (const float*)d_in[2];
    const float* whh = (const float*)d_in[3];
    const float* bih = (const float*)d_in[4];
    const float* bhh = (const float*)d_in[5];
    float* out = (float*)d_out;

    (void)in_sizes; (void)n_in; (void)out_size;

    gemm_gx<<<dim3(12, 512), 256>>>(x, wih, bih);
    gru_rec<<<NCTA, 512>>>(whh, bhh, len, out);
}

// round 8
// speedup vs baseline: 1.1120x; 1.1120x over previous
#include <cuda_runtime.h>

// Problem constants: T=1024, B=64, I=512, H=512, 3H=1536
#define NCTA 128
#define NTEAMS 4        // 4 teams x 32 CTAs; team tau owns b in {tau, tau+4, ..., tau+60}

// ---------------- device-global scratch (no allocation allowed) ----------------
__device__ float g_gx[100663296];                      // [1024*64, 1536] input gate pre-acts
__device__ __align__(16) float g_hP[2][NTEAMS][256][32]; // [buf][team][kp][tb*2+par] paired-unit h
__device__ unsigned int g_flag[NCTA];                  // per-CTA publish counters (monotonic)

// ---------------- f32x2 packed-math helpers (Blackwell, PTX-only path) ----------
__device__ __forceinline__ void ffma2(unsigned long long &acc, unsigned long long a,
                                      unsigned long long b) {
    asm("fma.rn.f32x2 %0, %1, %2, %0;" : "+l"(acc) : "l"(a), "l"(b));
}
__device__ __forceinline__ unsigned long long dup2(float a) {
    unsigned long long r; asm("mov.b64 %0, {%1, %1};" : "=l"(r) : "f"(a)); return r;
}
__device__ __forceinline__ unsigned long long pack2(float lo, float hi) {
    unsigned long long r; asm("mov.b64 %0, {%1, %2};" : "=l"(r) : "f"(lo), "f"(hi)); return r;
}
__device__ __forceinline__ float sum2(unsigned long long v) {
    float lo, hi; asm("mov.b64 {%0, %1}, %2;" : "=f"(lo), "=f"(hi) : "l"(v)); return lo + hi;
}
__device__ __forceinline__ float2 unpack2(unsigned long long v) {
    float2 f; asm("mov.b64 {%0, %1}, %2;" : "=f"(f.x), "=f"(f.y) : "l"(v)); return f;
}

// ---------------- flag primitives (gpu scope, L2-coherent) -----------------------
__device__ __forceinline__ unsigned int ld_acq(const unsigned int* p) {
    unsigned int v;
    asm volatile("ld.acquire.gpu.global.u32 %0, [%1];" : "=r"(v) : "l"(p) : "memory");
    return v;
}
__device__ __forceinline__ unsigned int ld_rlx(const unsigned int* p) {
    unsigned int v;
    asm volatile("ld.relaxed.gpu.global.u32 %0, [%1];" : "=r"(v) : "l"(p) : "memory");
    return v;
}
__device__ __forceinline__ void st_rel(unsigned int* p, unsigned int v) {
    asm volatile("st.release.gpu.global.u32 [%0], %1;" :: "l"(p), "r"(v) : "memory");
}
__device__ __forceinline__ void bar_sync(int id, int cnt) {
    asm volatile("bar.sync %0, %1;" :: "r"(id), "r"(cnt) : "memory");
}

// ---------------- dynamic SMEM layout (floats) -----------------------------------
#define WP_OFF   0                         // W paired-k: [48 rows][516]  (99,072 B)
#define WP_ROW   516
#define HS_OFF   (48 * 516)                // staged team h: [256 kp][36] (36,864 B)
#define HS_ROW   36
#define RED_OFF  (HS_OFF + 256 * 36)       // red: [2 par][2 ks][48 row][17] (26,112 B)
#define LENS_OFF (RED_OFF + 2 * 2 * 48 * 17)
#define SMEM_FLOATS (LENS_OFF + 16)
#define SMEM_BYTES  (SMEM_FLOATS * 4)
#define RED_AT(par, ksi, row, b) sm[RED_OFF + (((par) * 2 + (ksi)) * 48 + (row)) * 17 + (b)]

// =================================================================================
// Kernel A: gx[m][n] = sum_k X[m][k] * W[n][k] + bias[n]   (unchanged)
// =================================================================================
__global__ __launch_bounds__(256) void gemm_gx(const float* __restrict__ X,
                                               const float* __restrict__ W,
                                               const float* __restrict__ bias) {
    __shared__ __align__(16) float As[8][128];
    __shared__ __align__(16) float Bs[8][128];
    const int tid = threadIdx.x;
    const int m0 = blockIdx.y * 128;
    const int n0 = blockIdx.x * 128;
    const int tx = tid & 15;
    const int ty = tid >> 4;
    const int lrow = tid >> 1;
    const int lk = (tid & 1) * 4;

    unsigned long long acc[8][4];
#pragma unroll
    for (int i = 0; i < 8; i++)
#pragma unroll
        for (int jp = 0; jp < 4; jp++) acc[i][jp] = 0ull;

    const float* xg = X + (size_t)(m0 + lrow) * 512 + lk;
    const float* wg = W + (size_t)(n0 + lrow) * 512 + lk;

    for (int k0 = 0; k0 < 512; k0 += 8) {
        float4 av = *(const float4*)(xg + k0);
        float4 bv = *(const float4*)(wg + k0);
        __syncthreads();
        As[lk + 0][lrow] = av.x; As[lk + 1][lrow] = av.y;
        As[lk + 2][lrow] = av.z; As[lk + 3][lrow] = av.w;
        Bs[lk + 0][lrow] = bv.x; Bs[lk + 1][lrow] = bv.y;
        Bs[lk + 2][lrow] = bv.z; Bs[lk + 3][lrow] = bv.w;
        __syncthreads();
#pragma unroll
        for (int kk = 0; kk < 8; kk++) {
            float4 a0 = *(const float4*)&As[kk][ty * 8];
            float4 a1 = *(const float4*)&As[kk][ty * 8 + 4];
            float4 b0 = *(const float4*)&Bs[kk][tx * 8];
            float4 b1 = *(const float4*)&Bs[kk][tx * 8 + 4];
            unsigned long long bp0 = pack2(b0.x, b0.y);
            unsigned long long bp1 = pack2(b0.z, b0.w);
            unsigned long long bp2 = pack2(b1.x, b1.y);
            unsigned long long bp3 = pack2(b1.z, b1.w);
            float a[8] = {a0.x, a0.y, a0.z, a0.w, a1.x, a1.y, a1.z, a1.w};
#pragma unroll
            for (int i = 0; i < 8; i++) {
                unsigned long long ad = dup2(a[i]);
                ffma2(acc[i][0], ad, bp0);
                ffma2(acc[i][1], ad, bp1);
                ffma2(acc[i][2], ad, bp2);
                ffma2(acc[i][3], ad, bp3);
            }
        }
    }

    float bs[8];
#pragma unroll
    for (int c = 0; c < 8; c++) bs[c] = bias[n0 + tx * 8 + c];
#pragma unroll
    for (int i = 0; i < 8; i++) {
        size_t base = (size_t)(m0 + ty * 8 + i) * 1536 + n0 + tx * 8;
        float2 p0 = unpack2(acc[i][0]);
        float2 p1 = unpack2(acc[i][1]);
        float2 p2 = unpack2(acc[i][2]);
        float2 p3 = unpack2(acc[i][3]);
        float4 o0 = make_float4(p0.x + bs[0], p0.y + bs[1], p1.x + bs[2], p1.y + bs[3]);
        float4 o1 = make_float4(p2.x + bs[4], p2.y + bs[5], p3.x + bs[6], p3.y + bs[7]);
        *(float4*)&g_gx[base]     = o0;
        *(float4*)&g_gx[base + 4] = o1;
    }
}

// =================================================================================
// Kernel B: team-partitioned persistent GRU recurrence.
//   4 teams x 32 CTAs. Team tau owns sequences b = 4*i + tau (i = 0..15, lengths
//   descending in i). CTA c-of-team owns units j in [16c, 16c+16) -> 48 gate rows.
//   Sequences are independent -> sync + h exchange stay INSIDE the 32-CTA team.
//   Per step: poll team flags (warp 0 only) -> stage team h (32KB) into SMEM ->
//   FFMA2 accumulate (warp = rowgroup x kslice x bhalf; paired-k, W broadcast) ->
//   reduce -> gate math -> publish h pairs + release flag.
// =================================================================================
__global__ __launch_bounds__(512, 1) void gru_rec(const float* __restrict__ whh,
                                                  const float* __restrict__ bhh,
                                                  const int* __restrict__ lens,
                                                  float* __restrict__ out) {
    extern __shared__ __align__(16) float sm[];
    int* sm_lens = (int*)&sm[LENS_OFF];

    const int tid  = threadIdx.x;
    const int tau  = blockIdx.x >> 5;       // team 0..3
    const int c    = blockIdx.x & 31;       // CTA within team, owns units [16c,16c+16)
    const int wrp  = tid >> 5;
    const int lane = tid & 31;

    // FMA-phase warp mapping: (rowgroup 0..3 [12 rows], kslice 0..1 [128 kp], bhalf 0..1 [8 b])
    const int rg = wrp >> 2;
    const int ks = (wrp >> 1) & 1;
    const int bh = wrp & 1;
    const int q  = lane >> 2;                // k-sub 0..7
    const int p  = lane & 3;                 // b-pair 0..3
    const int b0 = bh * 8 + 2 * p;           // team-b
    const int rowbase = rg * 12;

    // gate-phase mapping (tid < 256): gu fast (shfl-pairable), gb slow
    const int gu = tid & 15;                 // unit-in-CTA
    const int gb = tid >> 4;                 // team-b 0..15
    const int bglob = 4 * gb + tau;          // global b
    const int j = 16 * c + gu;               // global unit

    // ---- preload W slice (48 rows x 512, paired-k = plain row copy) ----
    for (int idx = tid; idx < 48 * 128; idx += 512) {
        int row = idx >> 7;
        int k4  = (idx & 127) << 2;
        int g   = row >> 4;
        int u   = row & 15;
        *(float4*)&sm[WP_OFF + row * WP_ROW + k4] =
            *(const float4*)&whh[(size_t)(g * 512 + 16 * c + u) * 512 + k4];
    }
    if (tid < 16) sm_lens[tid] = lens[4 * tid + tau];   // team lengths (descending)

    const unsigned int F = ld_rlx(&g_flag[blockIdx.x]); // monotonic across graph replays

    float bh_r = 0.f, bh_z = 0.f, bh_n = 0.f;
    if (tid < 256) {
        bh_r = bhh[j];
        bh_z = bhh[512 + j];
        bh_n = bhh[1024 + j];
    }
    // h(0) = 0 for this CTA's 8 k-pairs (16 units) x 16 team-b
    if (tid < 256)
        __stcg(&g_hP[0][tau][8 * c + (tid >> 5)][tid & 31], 0.f);
    __syncthreads();
    const int maxlen_team = sm_lens[0];
    const int ml_bh = sm_lens[bh * 8];       // max length in this warp's b-half
    const int len_b = sm_lens[gb];
    if (tid == 0) st_rel(&g_flag[blockIdx.x], F + 1);   // h(0) published

    const unsigned int* fp = &g_flag[(tau << 5) + lane];
    float hreg = 0.f;

    for (int t = 0; t < 1024; t++) {
        if (t < maxlen_team) {
            // gx prefetch (static data; overlaps the poll)
            float gxr = 0.f, gxz = 0.f, gxn = 0.f;
            if (tid < 256) {
                const float* gxp = g_gx + (size_t)(t * 64 + bglob) * 1536 + j;
                gxr = gxp[0];
                gxz = gxp[512];
                gxn = gxp[1024];
            }

            // [poll] warp 0 waits for all 32 team CTAs to publish h(t)
            if (wrp == 0) {
                const unsigned int tgt = F + 1 + (unsigned)t;
                while (!__all_sync(0xffffffffu, ld_acq(fp) >= tgt)) {}
            }
            __syncthreads();                              // release poll; prev FMA done

            // [stage] team h(t): 256 kp x 32 floats -> hs (coalesced L2 reads)
            for (int s = tid; s < 2048; s += 512) {
                int kp = s >> 3;
                int f4 = (s & 7) << 2;
                float4 v = __ldcg((const float4*)&g_hP[t & 1][tau][kp][f4]);
                *(float4*)&sm[HS_OFF + kp * HS_ROW + f4] = v;
            }
            __syncthreads();

            // [FMA] 12 rows x 1 b-pair x 32 k per lane (skip if b-half is done)
            if (t < ml_bh) {
                unsigned long long accA[12], accB[12];
#pragma unroll
                for (int r = 0; r < 12; r++) { accA[r] = 0ull; accB[r] = 0ull; }

#pragma unroll
                for (int i = 0; i < 8; i++) {
                    int kp1 = ks * 128 + i * 16 + 2 * q;
                    // hs[kp][2b0..2b0+3] = {h[b0] pair, h[b0+1] pair} for this kp
                    ulonglong2 hA = *(const ulonglong2*)&sm[HS_OFF + kp1 * HS_ROW + 2 * b0];
                    ulonglong2 hB = *(const ulonglong2*)&sm[HS_OFF + (kp1 + 1) * HS_ROW + 2 * b0];
#pragma unroll
                    for (int r = 0; r < 12; r++) {
                        // 16B of W = pairs for kp1, kp1+1 (broadcast over p-lanes)
                        ulonglong2 wv = *(const ulonglong2*)
                            &sm[WP_OFF + (rowbase + r) * WP_ROW + 2 * kp1];
                        ffma2(accA[r], hA.x, wv.x);
                        ffma2(accA[r], hB.x, wv.y);
                        ffma2(accB[r], hA.y, wv.x);
                        ffma2(accB[r], hB.y, wv.y);
                    }
                }

                // fold k-parity + q (xor 4,8,16), lanes q==0 store per-kslice partials
#pragma unroll
                for (int r = 0; r < 12; r++) {
                    float sA = sum2(accA[r]);
                    float sB = sum2(accB[r]);
                    sA += __shfl_xor_sync(0xffffffffu, sA, 4);
                    sB += __shfl_xor_sync(0xffffffffu, sB, 4);
                    sA += __shfl_xor_sync(0xffffffffu, sA, 8);
                    sB += __shfl_xor_sync(0xffffffffu, sB, 8);
                    sA += __shfl_xor_sync(0xffffffffu, sA, 16);
                    sB += __shfl_xor_sync(0xffffffffu, sB, 16);
                    if (lane < 4) {
                        RED_AT(t & 1, ks, rowbase + r, b0)     = sA;
                        RED_AT(t & 1, ks, rowbase + r, b0 + 1) = sB;
                    }
                }
            }
            __syncthreads();                              // red[t&1] complete

            // [gate] 16 units x 16 team-b
            if (tid < 256) {
                float outv = 0.f;
                if (t < len_b) {
                    float ghr = bh_r + RED_AT(t & 1, 0, gu, gb)      + RED_AT(t & 1, 1, gu, gb);
                    float ghz = bh_z + RED_AT(t & 1, 0, 16 + gu, gb) + RED_AT(t & 1, 1, 16 + gu, gb);
                    float ghn = bh_n + RED_AT(t & 1, 0, 32 + gu, gb) + RED_AT(t & 1, 1, 32 + gu, gb);
                    float r = 1.f / (1.f + __expf(-(gxr + ghr)));
                    float z = 1.f / (1.f + __expf(-(gxz + ghz)));
                    float n = tanhf(gxn + r * ghn);
                    hreg = (1.f - z) * n + z * hreg;
                    outv = hreg;
                }
                // publish h(t+1) unit-pair via shfl partner (gu, gu^1 share gb)
                float hpart = __shfl_xor_sync(0xffffffffu, hreg, 1);
                if ((gu & 1) == 0) {
                    float2 v = make_float2(hreg, hpart);
                    __stcg((float2*)&g_hP[(t + 1) & 1][tau][8 * c + (gu >> 1)][2 * gb], v);
                }
                bar_sync(1, 256);                         // all h publishes done
                if (tid == 0) st_rel(&g_flag[blockIdx.x], F + 2 + (unsigned)t);

                out[(size_t)t * 32768 + bglob * 512 + j] = outv;  // off critical path
            }
        } else {
            // whole team finished: zero-fill remaining output rows (uniform branch)
            if (tid < 256)
                out[(size_t)t * 32768 + bglob * 512 + j] = 0.f;
        }
    }

    // h_last: [1, B, H] appended after output
    if (tid < 256)
        out[(size_t)1024 * 32768 + bglob * 512 + j] = hreg;
}

// =================================================================================
// Inputs (metadata order): x[T,B,I] f32, batch_lengths[B] i32, w_ih[3H,I] f32,
// w_hh[3H,H] f32, b_ih[3H] f32, b_hh[3H] f32.  Output: [T,B,H] then [1,B,H], fp32.
// =================================================================================
extern "C" void kernel_launch(void* const* d_in, const int* in_sizes, int n_in,
                              void* d_out, int out_size) {
    const float* x   = (const float*)d_in[0];
    const int*   len = (const int*)  d_in[1];
    const float* wih = (const float*)d_in[2];
    const float* whh = (const float*)d_in[3];
    const float* bih = (const float*)d_in[4];
    const float* bhh = (const float*)d_in[5];
    float* out = (float*)d_out;

    (void)in_sizes; (void)n_in; (void)out_size;

    cudaFuncSetAttribute(gru_rec, cudaFuncAttributeMaxDynamicSharedMemorySize, SMEM_BYTES);

    gemm_gx<<<dim3(12, 512), 256>>>(x, wih, bih);
    gru_rec<<<NCTA, 512, SMEM_BYTES>>>(whh, bhh, len, out);
}

// round 9
// speedup vs baseline: 1.1321x; 1.0180x over previous
#include <cuda_runtime.h>

// Problem constants: T=1024, B=64, I=512, H=512, 3H=1536
#define NCTA 128
#define NTEAMS 4        // 4 teams x 32 CTAs; team tau owns b in {tau, tau+4, ..., tau+60}

// ---------------- device-global scratch (no allocation allowed) ----------------
__device__ float g_gx[100663296];                      // [1024*64, 1536] input gate pre-acts
__device__ __align__(16) float g_hP[2][NTEAMS][256][32]; // [buf][team][kp][tb*2+par] paired-unit h
__device__ unsigned int g_flag[NCTA];                  // per-CTA publish counters (monotonic)

// ---------------- f32x2 packed-math helpers (Blackwell, PTX-only path) ----------
__device__ __forceinline__ void ffma2(unsigned long long &acc, unsigned long long a,
                                      unsigned long long b) {
    asm("fma.rn.f32x2 %0, %1, %2, %0;" : "+l"(acc) : "l"(a), "l"(b));
}
__device__ __forceinline__ unsigned long long dup2(float a) {
    unsigned long long r; asm("mov.b64 %0, {%1, %1};" : "=l"(r) : "f"(a)); return r;
}
__device__ __forceinline__ unsigned long long pack2(float lo, float hi) {
    unsigned long long r; asm("mov.b64 %0, {%1, %2};" : "=l"(r) : "f"(lo), "f"(hi)); return r;
}
__device__ __forceinline__ float sum2(unsigned long long v) {
    float lo, hi; asm("mov.b64 {%0, %1}, %2;" : "=f"(lo), "=f"(hi) : "l"(v)); return lo + hi;
}
__device__ __forceinline__ float2 unpack2(unsigned long long v) {
    float2 f; asm("mov.b64 {%0, %1}, %2;" : "=f"(f.x), "=f"(f.y) : "l"(v)); return f;
}

// ---------------- flag primitives (gpu scope, L2-coherent) -----------------------
__device__ __forceinline__ unsigned int ld_acq(const unsigned int* p) {
    unsigned int v;
    asm volatile("ld.acquire.gpu.global.u32 %0, [%1];" : "=r"(v) : "l"(p) : "memory");
    return v;
}
__device__ __forceinline__ unsigned int ld_rlx(const unsigned int* p) {
    unsigned int v;
    asm volatile("ld.relaxed.gpu.global.u32 %0, [%1];" : "=r"(v) : "l"(p) : "memory");
    return v;
}
__device__ __forceinline__ void st_rel(unsigned int* p, unsigned int v) {
    asm volatile("st.release.gpu.global.u32 [%0], %1;" :: "l"(p), "r"(v) : "memory");
}
__device__ __forceinline__ void bar_sync(int id, int cnt) {
    asm volatile("bar.sync %0, %1;" :: "r"(id), "r"(cnt) : "memory");
}

// ---------------- dynamic SMEM layout (floats) -----------------------------------
#define WP_OFF   0                         // W paired-k: [48 rows][516]  (99,072 B)
#define WP_ROW   516
#define HS_OFF   (48 * 516)                // staged team h: [256 kp][36] (36,864 B)
#define HS_ROW   36
#define RED_OFF  (HS_OFF + 256 * 36)       // red: [2 par][2 ks][48 row][17] (26,112 B)
#define LENS_OFF (RED_OFF + 2 * 2 * 48 * 17)
#define SMEM_FLOATS (LENS_OFF + 16)
#define SMEM_BYTES  (SMEM_FLOATS * 4)
#define RED_AT(par, ksi, row, b) sm[RED_OFF + (((par) * 2 + (ksi)) * 48 + (row)) * 17 + (b)]

// =================================================================================
// Kernel A: gx[m][n] = sum_k X[m][k] * W[n][k] + bias[n]   (unchanged)
// =================================================================================
__global__ __launch_bounds__(256) void gemm_gx(const float* __restrict__ X,
                                               const float* __restrict__ W,
                                               const float* __restrict__ bias) {
    __shared__ __align__(16) float As[8][128];
    __shared__ __align__(16) float Bs[8][128];
    const int tid = threadIdx.x;
    const int m0 = blockIdx.y * 128;
    const int n0 = blockIdx.x * 128;
    const int tx = tid & 15;
    const int ty = tid >> 4;
    const int lrow = tid >> 1;
    const int lk = (tid & 1) * 4;

    unsigned long long acc[8][4];
#pragma unroll
    for (int i = 0; i < 8; i++)
#pragma unroll
        for (int jp = 0; jp < 4; jp++) acc[i][jp] = 0ull;

    const float* xg = X + (size_t)(m0 + lrow) * 512 + lk;
    const float* wg = W + (size_t)(n0 + lrow) * 512 + lk;

    for (int k0 = 0; k0 < 512; k0 += 8) {
        float4 av = *(const float4*)(xg + k0);
        float4 bv = *(const float4*)(wg + k0);
        __syncthreads();
        As[lk + 0][lrow] = av.x; As[lk + 1][lrow] = av.y;
        As[lk + 2][lrow] = av.z; As[lk + 3][lrow] = av.w;
        Bs[lk + 0][lrow] = bv.x; Bs[lk + 1][lrow] = bv.y;
        Bs[lk + 2][lrow] = bv.z; Bs[lk + 3][lrow] = bv.w;
        __syncthreads();
#pragma unroll
        for (int kk = 0; kk < 8; kk++) {
            float4 a0 = *(const float4*)&As[kk][ty * 8];
            float4 a1 = *(const float4*)&As[kk][ty * 8 + 4];
            float4 b0 = *(const float4*)&Bs[kk][tx * 8];
            float4 b1 = *(const float4*)&Bs[kk][tx * 8 + 4];
            unsigned long long bp0 = pack2(b0.x, b0.y);
            unsigned long long bp1 = pack2(b0.z, b0.w);
            unsigned long long bp2 = pack2(b1.x, b1.y);
            unsigned long long bp3 = pack2(b1.z, b1.w);
            float a[8] = {a0.x, a0.y, a0.z, a0.w, a1.x, a1.y, a1.z, a1.w};
#pragma unroll
            for (int i = 0; i < 8; i++) {
                unsigned long long ad = dup2(a[i]);
                ffma2(acc[i][0], ad, bp0);
                ffma2(acc[i][1], ad, bp1);
                ffma2(acc[i][2], ad, bp2);
                ffma2(acc[i][3], ad, bp3);
            }
        }
    }

    float bs[8];
#pragma unroll
    for (int c = 0; c < 8; c++) bs[c] = bias[n0 + tx * 8 + c];
#pragma unroll
    for (int i = 0; i < 8; i++) {
        size_t base = (size_t)(m0 + ty * 8 + i) * 1536 + n0 + tx * 8;
        float2 p0 = unpack2(acc[i][0]);
        float2 p1 = unpack2(acc[i][1]);
        float2 p2 = unpack2(acc[i][2]);
        float2 p3 = unpack2(acc[i][3]);
        float4 o0 = make_float4(p0.x + bs[0], p0.y + bs[1], p1.x + bs[2], p1.y + bs[3]);
        float4 o1 = make_float4(p2.x + bs[4], p2.y + bs[5], p3.x + bs[6], p3.y + bs[7]);
        *(float4*)&g_gx[base]     = o0;
        *(float4*)&g_gx[base + 4] = o1;
    }
}

// =================================================================================
// Kernel B: team-partitioned persistent GRU recurrence.
//   4 teams x 32 CTAs. Team tau owns sequences b = 4*i + tau (i = 0..15, lengths
//   descending in i). CTA c-of-team owns units j in [16c, 16c+16) -> 48 gate rows.
//   Sequences are independent -> sync + h exchange stay INSIDE the 32-CTA team.
//   Per step: poll team flags (warp 0 only) -> stage team h (32KB) into SMEM ->
//   FFMA2 accumulate (warp = rowgroup x kslice x bhalf; paired-k, W broadcast) ->
//   reduce -> gate math -> publish h pairs + release flag.
// =================================================================================
__global__ __launch_bounds__(512, 1) void gru_rec(const float* __restrict__ whh,
                                                  const float* __restrict__ bhh,
                                                  const int* __restrict__ lens,
                                                  float* __restrict__ out) {
    extern __shared__ __align__(16) float sm[];
    int* sm_lens = (int*)&sm[LENS_OFF];

    const int tid  = threadIdx.x;
    const int tau  = blockIdx.x >> 5;       // team 0..3
    const int c    = blockIdx.x & 31;       // CTA within team, owns units [16c,16c+16)
    const int wrp  = tid >> 5;
    const int lane = tid & 31;

    // FMA-phase warp mapping: (rowgroup 0..3 [12 rows], kslice 0..1 [128 kp], bhalf 0..1 [8 b])
    const int rg = wrp >> 2;
    const int ks = (wrp >> 1) & 1;
    const int bh = wrp & 1;
    const int q  = lane >> 2;                // k-sub 0..7
    const int p  = lane & 3;                 // b-pair 0..3
    const int b0 = bh * 8 + 2 * p;           // team-b
    const int rowbase = rg * 12;

    // gate-phase mapping (tid < 256): gu fast (shfl-pairable), gb slow
    const int gu = tid & 15;                 // unit-in-CTA
    const int gb = tid >> 4;                 // team-b 0..15
    const int bglob = 4 * gb + tau;          // global b
    const int j = 16 * c + gu;               // global unit

    // ---- preload W slice (48 rows x 512, paired-k = plain row copy) ----
    for (int idx = tid; idx < 48 * 128; idx += 512) {
        int row = idx >> 7;
        int k4  = (idx & 127) << 2;
        int g   = row >> 4;
        int u   = row & 15;
        *(float4*)&sm[WP_OFF + row * WP_ROW + k4] =
            *(const float4*)&whh[(size_t)(g * 512 + 16 * c + u) * 512 + k4];
    }
    if (tid < 16) sm_lens[tid] = lens[4 * tid + tau];   // team lengths (descending)

    const unsigned int F = ld_rlx(&g_flag[blockIdx.x]); // monotonic across graph replays

    float bh_r = 0.f, bh_z = 0.f, bh_n = 0.f;
    if (tid < 256) {
        bh_r = bhh[j];
        bh_z = bhh[512 + j];
        bh_n = bhh[1024 + j];
    }
    // h(0) = 0 for this CTA's 8 k-pairs (16 units) x 16 team-b
    if (tid < 256)
        __stcg(&g_hP[0][tau][8 * c + (tid >> 5)][tid & 31], 0.f);
    __syncthreads();
    const int maxlen_team = sm_lens[0];
    const int ml_bh = sm_lens[bh * 8];       // max length in this warp's b-half
    const int len_b = sm_lens[gb];
    if (tid == 0) st_rel(&g_flag[blockIdx.x], F + 1);   // h(0) published

    const unsigned int* fp = &g_flag[(tau << 5) + lane];
    float hreg = 0.f;

    for (int t = 0; t < 1024; t++) {
        if (t < maxlen_team) {
            // gx prefetch (static data; overlaps the poll)
            float gxr = 0.f, gxz = 0.f, gxn = 0.f;
            if (tid < 256) {
                const float* gxp = g_gx + (size_t)(t * 64 + bglob) * 1536 + j;
                gxr = gxp[0];
                gxz = gxp[512];
                gxn = gxp[1024];
            }

            // [poll] warp 0 waits for all 32 team CTAs to publish h(t)
            if (wrp == 0) {
                const unsigned int tgt = F + 1 + (unsigned)t;
                while (!__all_sync(0xffffffffu, ld_acq(fp) >= tgt)) {}
            }
            __syncthreads();                              // release poll; prev FMA done

            // [stage] team h(t): 256 kp x 32 floats -> hs (coalesced L2 reads)
            for (int s = tid; s < 2048; s += 512) {
                int kp = s >> 3;
                int f4 = (s & 7) << 2;
                float4 v = __ldcg((const float4*)&g_hP[t & 1][tau][kp][f4]);
                *(float4*)&sm[HS_OFF + kp * HS_ROW + f4] = v;
            }
            __syncthreads();

            // [FMA] 12 rows x 1 b-pair x 32 k per lane (skip if b-half is done)
            if (t < ml_bh) {
                unsigned long long accA[12], accB[12];
#pragma unroll
                for (int r = 0; r < 12; r++) { accA[r] = 0ull; accB[r] = 0ull; }

#pragma unroll
                for (int i = 0; i < 8; i++) {
                    int kp1 = ks * 128 + i * 16 + 2 * q;
                    // hs[kp][2b0..2b0+3] = {h[b0] pair, h[b0+1] pair} for this kp
                    ulonglong2 hA = *(const ulonglong2*)&sm[HS_OFF + kp1 * HS_ROW + 2 * b0];
                    ulonglong2 hB = *(const ulonglong2*)&sm[HS_OFF + (kp1 + 1) * HS_ROW + 2 * b0];
#pragma unroll
                    for (int r = 0; r < 12; r++) {
                        // 16B of W = pairs for kp1, kp1+1 (broadcast over p-lanes)
                        ulonglong2 wv = *(const ulonglong2*)
                            &sm[WP_OFF + (rowbase + r) * WP_ROW + 2 * kp1];
                        ffma2(accA[r], hA.x, wv.x);
                        ffma2(accA[r], hB.x, wv.y);
                        ffma2(accB[r], hA.y, wv.x);
                        ffma2(accB[r], hB.y, wv.y);
                    }
                }

                // fold k-parity + q (xor 4,8,16), lanes q==0 store per-kslice partials
#pragma unroll
                for (int r = 0; r < 12; r++) {
                    float sA = sum2(accA[r]);
                    float sB = sum2(accB[r]);
                    sA += __shfl_xor_sync(0xffffffffu, sA, 4);
                    sB += __shfl_xor_sync(0xffffffffu, sB, 4);
                    sA += __shfl_xor_sync(0xffffffffu, sA, 8);
                    sB += __shfl_xor_sync(0xffffffffu, sB, 8);
                    sA += __shfl_xor_sync(0xffffffffu, sA, 16);
                    sB += __shfl_xor_sync(0xffffffffu, sB, 16);
                    if (lane < 4) {
                        RED_AT(t & 1, ks, rowbase + r, b0)     = sA;
                        RED_AT(t & 1, ks, rowbase + r, b0 + 1) = sB;
                    }
                }
            }
            __syncthreads();                              // red[t&1] complete

            // [gate] 16 units x 16 team-b
            if (tid < 256) {
                float outv = 0.f;
                if (t < len_b) {
                    float ghr = bh_r + RED_AT(t & 1, 0, gu, gb)      + RED_AT(t & 1, 1, gu, gb);
                    float ghz = bh_z + RED_AT(t & 1, 0, 16 + gu, gb) + RED_AT(t & 1, 1, 16 + gu, gb);
                    float ghn = bh_n + RED_AT(t & 1, 0, 32 + gu, gb) + RED_AT(t & 1, 1, 32 + gu, gb);
                    float r = 1.f / (1.f + __expf(-(gxr + ghr)));
                    float z = 1.f / (1.f + __expf(-(gxz + ghz)));
                    float n = tanhf(gxn + r * ghn);
                    hreg = (1.f - z) * n + z * hreg;
                    outv = hreg;
                }
                // publish h(t+1) unit-pair via shfl partner (gu, gu^1 share gb)
                float hpart = __shfl_xor_sync(0xffffffffu, hreg, 1);
                if ((gu & 1) == 0) {
                    float2 v = make_float2(hreg, hpart);
                    __stcg((float2*)&g_hP[(t + 1) & 1][tau][8 * c + (gu >> 1)][2 * gb], v);
                }
                bar_sync(1, 256);                         // all h publishes done
                if (tid == 0) st_rel(&g_flag[blockIdx.x], F + 2 + (unsigned)t);

                out[(size_t)t * 32768 + bglob * 512 + j] = outv;  // off critical path
            }
        } else {
            // whole team finished: zero-fill remaining output rows (uniform branch)
            if (tid < 256)
                out[(size_t)t * 32768 + bglob * 512 + j] = 0.f;
        }
    }

    // h_last: [1, B, H] appended after output
    if (tid < 256)
        out[(size_t)1024 * 32768 + bglob * 512 + j] = hreg;
}

// =================================================================================
// Inputs (metadata order): x[T,B,I] f32, batch_lengths[B] i32, w_ih[3H,I] f32,
// w_hh[3H,H] f32, b_ih[3H] f32, b_hh[3H] f32.  Output: [T,B,H] then [1,B,H], fp32.
// =================================================================================
extern "C" void kernel_launch(void* const* d_in, const int* in_sizes, int n_in,
                              void* d_out, int out_size) {
    const float* x   = (const float*)d_in[0];
    const int*   len = (const int*)  d_in[1];
    const float* wih = (const float*)d_in[2];
    const float* whh = (const float*)d_in[3];
    const float* bih = (const float*)d_in[4];
    const float* bhh = (const float*)d_in[5];
    float* out = (float*)d_out;

    (void)in_sizes; (void)n_in; (void)out_size;

    cudaFuncSetAttribute(gru_rec, cudaFuncAttributeMaxDynamicSharedMemorySize, SMEM_BYTES);

    gemm_gx<<<dim3(12, 512), 256>>>(x, wih, bih);
    gru_rec<<<NCTA, 512, SMEM_BYTES>>>(whh, bhh, len, out);
}

// round 10
// speedup vs baseline: 1.1693x; 1.0329x over previous
#include <cuda_runtime.h>

// Problem constants: T=1024, B=64, I=512, H=512, 3H=1536
#define NCTA 128
#define NTEAMS 4        // 4 teams x 32 CTAs; team tau owns b in {tau, tau+4, ..., tau+60}
#define NTHR 768        // 24 warps: 6 rowgroups x 2 kslices x 2 bhalves

// ---------------- device-global scratch (no allocation allowed) ----------------
__device__ float g_gx[100663296];                      // [1024*64, 1536] input gate pre-acts
__device__ __align__(16) float g_hP[2][NTEAMS][256][32]; // [buf][team][kp][tb*2+par]
__device__ unsigned int g_flag[NCTA];                  // per-CTA publish counters (monotonic)

// ---------------- f32x2 packed-math helpers (Blackwell, PTX-only path) ----------
__device__ __forceinline__ void ffma2(unsigned long long &acc, unsigned long long a,
                                      unsigned long long b) {
    asm("fma.rn.f32x2 %0, %1, %2, %0;" : "+l"(acc) : "l"(a), "l"(b));
}
__device__ __forceinline__ unsigned long long dup2(float a) {
    unsigned long long r; asm("mov.b64 %0, {%1, %1};" : "=l"(r) : "f"(a)); return r;
}
__device__ __forceinline__ unsigned long long pack2(float lo, float hi) {
    unsigned long long r; asm("mov.b64 %0, {%1, %2};" : "=l"(r) : "f"(lo), "f"(hi)); return r;
}
__device__ __forceinline__ float sum2(unsigned long long v) {
    float lo, hi; asm("mov.b64 {%0, %1}, %2;" : "=f"(lo), "=f"(hi) : "l"(v)); return lo + hi;
}
__device__ __forceinline__ float2 unpack2(unsigned long long v) {
    float2 f; asm("mov.b64 {%0, %1}, %2;" : "=f"(f.x), "=f"(f.y) : "l"(v)); return f;
}

// ---------------- flag primitives (gpu scope, L2-coherent) -----------------------
__device__ __forceinline__ unsigned int ld_acq(const unsigned int* p) {
    unsigned int v;
    asm volatile("ld.acquire.gpu.global.u32 %0, [%1];" : "=r"(v) : "l"(p) : "memory");
    return v;
}
__device__ __forceinline__ unsigned int ld_rlx(const unsigned int* p) {
    unsigned int v;
    asm volatile("ld.relaxed.gpu.global.u32 %0, [%1];" : "=r"(v) : "l"(p) : "memory");
    return v;
}
__device__ __forceinline__ void st_rel(unsigned int* p, unsigned int v) {
    asm volatile("st.release.gpu.global.u32 [%0], %1;" :: "l"(p), "r"(v) : "memory");
}
__device__ __forceinline__ void bar_sync(int id, int cnt) {
    asm volatile("bar.sync %0, %1;" :: "r"(id), "r"(cnt) : "memory");
}

// ---------------- dynamic SMEM layout (floats) -----------------------------------
#define WP_OFF   0                         // W: [48 rows][516]           (99,072 B)
#define WP_ROW   516
#define HS_OFF   (48 * 516)                // staged team h: [256 kp][36] (36,864 B)
#define HS_ROW   36
#define RED_OFF  (HS_OFF + 256 * 36)       // red: [2 par][2 ks][48][17]  (13,056 B)
#define LENS_OFF (RED_OFF + 2 * 2 * 48 * 17)
#define SMEM_FLOATS (LENS_OFF + 16)
#define SMEM_BYTES  (SMEM_FLOATS * 4)
#define RED_AT(par, ksi, row, b) sm[RED_OFF + (((par) * 2 + (ksi)) * 48 + (row)) * 17 + (b)]

// =================================================================================
// Kernel A: gx[m][n] = sum_k X[m][k] * W[n][k] + bias[n]   (unchanged)
// =================================================================================
__global__ __launch_bounds__(256) void gemm_gx(const float* __restrict__ X,
                                               const float* __restrict__ W,
                                               const float* __restrict__ bias) {
    __shared__ __align__(16) float As[8][128];
    __shared__ __align__(16) float Bs[8][128];
    const int tid = threadIdx.x;
    const int m0 = blockIdx.y * 128;
    const int n0 = blockIdx.x * 128;
    const int tx = tid & 15;
    const int ty = tid >> 4;
    const int lrow = tid >> 1;
    const int lk = (tid & 1) * 4;

    unsigned long long acc[8][4];
#pragma unroll
    for (int i = 0; i < 8; i++)
#pragma unroll
        for (int jp = 0; jp < 4; jp++) acc[i][jp] = 0ull;

    const float* xg = X + (size_t)(m0 + lrow) * 512 + lk;
    const float* wg = W + (size_t)(n0 + lrow) * 512 + lk;

    for (int k0 = 0; k0 < 512; k0 += 8) {
        float4 av = *(const float4*)(xg + k0);
        float4 bv = *(const float4*)(wg + k0);
        __syncthreads();
        As[lk + 0][lrow] = av.x; As[lk + 1][lrow] = av.y;
        As[lk + 2][lrow] = av.z; As[lk + 3][lrow] = av.w;
        Bs[lk + 0][lrow] = bv.x; Bs[lk + 1][lrow] = bv.y;
        Bs[lk + 2][lrow] = bv.z; Bs[lk + 3][lrow] = bv.w;
        __syncthreads();
#pragma unroll
        for (int kk = 0; kk < 8; kk++) {
            float4 a0 = *(const float4*)&As[kk][ty * 8];
            float4 a1 = *(const float4*)&As[kk][ty * 8 + 4];
            float4 b0 = *(const float4*)&Bs[kk][tx * 8];
            float4 b1 = *(const float4*)&Bs[kk][tx * 8 + 4];
            unsigned long long bp0 = pack2(b0.x, b0.y);
            unsigned long long bp1 = pack2(b0.z, b0.w);
            unsigned long long bp2 = pack2(b1.x, b1.y);
            unsigned long long bp3 = pack2(b1.z, b1.w);
            float a[8] = {a0.x, a0.y, a0.z, a0.w, a1.x, a1.y, a1.z, a1.w};
#pragma unroll
            for (int i = 0; i < 8; i++) {
                unsigned long long ad = dup2(a[i]);
                ffma2(acc[i][0], ad, bp0);
                ffma2(acc[i][1], ad, bp1);
                ffma2(acc[i][2], ad, bp2);
                ffma2(acc[i][3], ad, bp3);
            }
        }
    }

    float bs[8];
#pragma unroll
    for (int c = 0; c < 8; c++) bs[c] = bias[n0 + tx * 8 + c];
#pragma unroll
    for (int i = 0; i < 8; i++) {
        size_t base = (size_t)(m0 + ty * 8 + i) * 1536 + n0 + tx * 8;
        float2 p0 = unpack2(acc[i][0]);
        float2 p1 = unpack2(acc[i][1]);
        float2 p2 = unpack2(acc[i][2]);
        float2 p3 = unpack2(acc[i][3]);
        float4 o0 = make_float4(p0.x + bs[0], p0.y + bs[1], p1.x + bs[2], p1.y + bs[3]);
        float4 o1 = make_float4(p2.x + bs[4], p2.y + bs[5], p3.x + bs[6], p3.y + bs[7]);
        *(float4*)&g_gx[base]     = o0;
        *(float4*)&g_gx[base + 4] = o1;
    }
}

// =================================================================================
// Kernel B: team-partitioned persistent GRU recurrence, 768 threads (24 warps).
//   4 teams x 32 CTAs; team tau owns b = 4i + tau; CTA owns units [16c,16c+16).
//   Warp = rowgroup(6 x 8 rows) x kslice(2 x 128 kp) x bhalf(2 x 8 b).
//   Lane = q(8 kp-subs) x p(4 b-pairs). Per lane: 8 rows x 32 k x 2 b,
//   acc = 8 u64 pairs (k-parity f32x2). 6 warps/SMSP for latency hiding.
// =================================================================================
__global__ __launch_bounds__(NTHR, 1) void gru_rec(const float* __restrict__ whh,
                                                   const float* __restrict__ bhh,
                                                   const int* __restrict__ lens,
                                                   float* __restrict__ out) {
    extern __shared__ __align__(16) float sm[];
    int* sm_lens = (int*)&sm[LENS_OFF];

    const int tid  = threadIdx.x;
    const int tau  = blockIdx.x >> 5;        // team 0..3
    const int c    = blockIdx.x & 31;        // CTA within team
    const int wrp  = tid >> 5;
    const int lane = tid & 31;

    // FMA-phase warp mapping
    const int rg = wrp >> 2;                 // rowgroup 0..5 (8 rows each)
    const int ks = (wrp >> 1) & 1;           // kslice 0..1 (128 kp each)
    const int bh = wrp & 1;                  // bhalf 0..1 (8 b each)
    const int q  = lane >> 2;                // kp-sub 0..7
    const int p  = lane & 3;                 // b-pair 0..3
    const int b0 = bh * 8 + 2 * p;           // team-b
    const int rowbase = rg * 8;

    // gate-phase mapping (tid < 256)
    const int gu = tid & 15;                 // unit-in-CTA
    const int gb = tid >> 4;                 // team-b 0..15 (only valid tid<256)
    const int bglob = 4 * (gb & 15) + tau;
    const int j = 16 * c + gu;

    // ---- preload W slice (48 rows x 512) ----
    for (int idx = tid; idx < 48 * 128; idx += NTHR) {
        int row = idx >> 7;
        int k4  = (idx & 127) << 2;
        int g   = row >> 4;
        int u   = row & 15;
        *(float4*)&sm[WP_OFF + row * WP_ROW + k4] =
            *(const float4*)&whh[(size_t)(g * 512 + 16 * c + u) * 512 + k4];
    }
    if (tid < 16) sm_lens[tid] = lens[4 * tid + tau];

    const unsigned int F = ld_rlx(&g_flag[blockIdx.x]); // monotonic across replays

    float bh_r = 0.f, bh_z = 0.f, bh_n = 0.f;
    if (tid < 256) {
        bh_r = bhh[j];
        bh_z = bhh[512 + j];
        bh_n = bhh[1024 + j];
    }
    // h(0) = 0 for this CTA's 8 kp x 32 floats
    if (tid < 256)
        __stcg(&g_hP[0][tau][8 * c + (tid >> 5)][tid & 31], 0.f);
    __syncthreads();
    const int maxlen_team = sm_lens[0];
    const int ml_bh = sm_lens[bh * 8];       // warp b-half max length (descending)
    const int len_b = (tid < 256) ? sm_lens[gb] : 0;
    if (tid == 0) st_rel(&g_flag[blockIdx.x], F + 1);   // h(0) published

    const unsigned int* fp = &g_flag[(tau << 5) + lane];
    float hreg = 0.f;

    for (int t = 0; t < 1024; t++) {
        if (t < maxlen_team) {
            // gx prefetch (overlaps poll)
            float gxr = 0.f, gxz = 0.f, gxn = 0.f;
            if (tid < 256) {
                const float* gxp = g_gx + (size_t)(t * 64 + bglob) * 1536 + j;
                gxr = gxp[0];
                gxz = gxp[512];
                gxn = gxp[1024];
            }

            // [poll] warp 0 waits for all 32 team CTAs to publish h(t)
            if (wrp == 0) {
                const unsigned int tgt = F + 1 + (unsigned)t;
                while (!__all_sync(0xffffffffu, ld_acq(fp) >= tgt)) {}
            }
            __syncthreads();

            // [stage] team h(t): 256 kp x 32 floats (coalesced L2 reads)
            for (int s = tid; s < 2048; s += NTHR) {
                int kp = s >> 3;
                int f4 = (s & 7) << 2;
                float4 v = __ldcg((const float4*)&g_hP[t & 1][tau][kp][f4]);
                *(float4*)&sm[HS_OFF + kp * HS_ROW + f4] = v;
            }
            __syncthreads();

            // [FMA] 8 rows x 1 b-pair x 32 k per lane (skip if b-half done)
            if (t < ml_bh) {
                unsigned long long accA[8], accB[8];
#pragma unroll
                for (int r = 0; r < 8; r++) { accA[r] = 0ull; accB[r] = 0ull; }

#pragma unroll
                for (int i = 0; i < 8; i++) {
                    int kp1 = ks * 128 + i * 16 + 2 * q;
                    ulonglong2 hA = *(const ulonglong2*)&sm[HS_OFF + kp1 * HS_ROW + 2 * b0];
                    ulonglong2 hB = *(const ulonglong2*)&sm[HS_OFF + (kp1 + 1) * HS_ROW + 2 * b0];
#pragma unroll
                    for (int r = 0; r < 8; r++) {
                        ulonglong2 wv = *(const ulonglong2*)
                            &sm[WP_OFF + (rowbase + r) * WP_ROW + 2 * kp1];
                        ffma2(accA[r], hA.x, wv.x);
                        ffma2(accA[r], hB.x, wv.y);
                        ffma2(accB[r], hA.y, wv.x);
                        ffma2(accB[r], hB.y, wv.y);
                    }
                }

                // fold k-parity + q (xor 4,8,16); q==0 lanes store partials
#pragma unroll
                for (int r = 0; r < 8; r++) {
                    float sA = sum2(accA[r]);
                    float sB = sum2(accB[r]);
                    sA += __shfl_xor_sync(0xffffffffu, sA, 4);
                    sB += __shfl_xor_sync(0xffffffffu, sB, 4);
                    sA += __shfl_xor_sync(0xffffffffu, sA, 8);
                    sB += __shfl_xor_sync(0xffffffffu, sB, 8);
                    sA += __shfl_xor_sync(0xffffffffu, sA, 16);
                    sB += __shfl_xor_sync(0xffffffffu, sB, 16);
                    if (lane < 4) {
                        RED_AT(t & 1, ks, rowbase + r, b0)     = sA;
                        RED_AT(t & 1, ks, rowbase + r, b0 + 1) = sB;
                    }
                }
            }
            __syncthreads();                              // red[t&1] complete

            // [gate] 16 units x 16 team-b
            if (tid < 256) {
                float outv = 0.f;
                if (t < len_b) {
                    float ghr = bh_r + RED_AT(t & 1, 0, gu, gb)      + RED_AT(t & 1, 1, gu, gb);
                    float ghz = bh_z + RED_AT(t & 1, 0, 16 + gu, gb) + RED_AT(t & 1, 1, 16 + gu, gb);
                    float ghn = bh_n + RED_AT(t & 1, 0, 32 + gu, gb) + RED_AT(t & 1, 1, 32 + gu, gb);
                    float r = 1.f / (1.f + __expf(-(gxr + ghr)));
                    float z = 1.f / (1.f + __expf(-(gxz + ghz)));
                    float n = tanhf(gxn + r * ghn);
                    hreg = (1.f - z) * n + z * hreg;
                    outv = hreg;
                }
                // publish h(t+1) unit-pair via shfl partner
                float hpart = __shfl_xor_sync(0xffffffffu, hreg, 1);
                if ((gu & 1) == 0) {
                    float2 v = make_float2(hreg, hpart);
                    __stcg((float2*)&g_hP[(t + 1) & 1][tau][8 * c + (gu >> 1)][2 * gb], v);
                }
                bar_sync(1, 256);                         // all h publishes done
                if (tid == 0) st_rel(&g_flag[blockIdx.x], F + 2 + (unsigned)t);

                out[(size_t)t * 32768 + bglob * 512 + j] = outv;
            }
        } else {
            // whole team finished: zero-fill remaining output rows
            if (tid < 256)
                out[(size_t)t * 32768 + bglob * 512 + j] = 0.f;
        }
    }

    // h_last: [1, B, H]
    if (tid < 256)
        out[(size_t)1024 * 32768 + bglob * 512 + j] = hreg;
}

// =================================================================================
// Inputs (metadata order): x[T,B,I] f32, batch_lengths[B] i32, w_ih[3H,I] f32,
// w_hh[3H,H] f32, b_ih[3H] f32, b_hh[3H] f32.  Output: [T,B,H] then [1,B,H], fp32.
// =================================================================================
extern "C" void kernel_launch(void* const* d_in, const int* in_sizes, int n_in,
                              void* d_out, int out_size) {
    const float* x   = (const float*)d_in[0];
    const int*   len = (const int*)  d_in[1];
    const float* wih = (const float*)d_in[2];
    const float* whh = (const float*)d_in[3];
    const float* bih = (const float*)d_in[4];
    const float* bhh = (const float*)d_in[5];
    float* out = (float*)d_out;

    (void)in_sizes; (void)n_in; (void)out_size;

    cudaFuncSetAttribute(gru_rec, cudaFuncAttributeMaxDynamicSharedMemorySize, SMEM_BYTES);

    gemm_gx<<<dim3(12, 512), 256>>>(x, wih, bih);
    gru_rec<<<NCTA, NTHR, SMEM_BYTES>>>(whh, bhh, len, out);
}